// round 11
// baseline (speedup 1.0000x reference)
#include <cuda_runtime.h>
#include <cuda_bf16.h>
#include <cstdint>

// Embedding gather: out[row, :] = w[x[row], :]
// x: [16384] int32, w: [50257, 1024] fp32, out: [16384, 1024] fp32
//
// Proven steady-state policy (graph replay, same x each iter):
//   - gathered w rows: ld.global.nc + L2::evict_last  (hot ~57 MB stays in L2)
//   - out: streaming .cs stores (write stream must NOT occupy L2; every
//     retention-priority store variant measured ~4.5 us slower)
// This round: 128-bit -> 256-bit accesses (Blackwell v8.f32, 32B aligned).
// Halves LDG/STG instruction count, L1 wavefronts, and store issue cost.
// 128 threads/block, each owns one 32-byte slot, 8 rows front-batched (MLP=8).

#define EMB_DIM 1024
#define V8_PER_ROW (EMB_DIM / 8)    // 128 x 32B slots per row
#define ROWS_PER_BLOCK 8

struct f8 { float v[8]; };

__device__ __forceinline__ f8 ldg8_el(const float* p, uint64_t pol) {
    f8 r;
    asm volatile("ld.global.nc.L2::cache_hint.v8.f32 "
                 "{%0,%1,%2,%3,%4,%5,%6,%7}, [%8], %9;"
                 : "=f"(r.v[0]), "=f"(r.v[1]), "=f"(r.v[2]), "=f"(r.v[3]),
                   "=f"(r.v[4]), "=f"(r.v[5]), "=f"(r.v[6]), "=f"(r.v[7])
                 : "l"(p), "l"(pol));
    return r;
}

__device__ __forceinline__ void stg8_cs(float* p, const f8& r) {
    asm volatile("st.global.cs.v8.f32 [%0], {%1,%2,%3,%4,%5,%6,%7,%8};"
                 :: "l"(p),
                    "f"(r.v[0]), "f"(r.v[1]), "f"(r.v[2]), "f"(r.v[3]),
                    "f"(r.v[4]), "f"(r.v[5]), "f"(r.v[6]), "f"(r.v[7])
                 : "memory");
}

__global__ void __launch_bounds__(128) embedding_gather_kernel(
    const int* __restrict__ x,
    const float* __restrict__ w,
    float* __restrict__ out,
    int n_rows)
{
    uint64_t pol;
    asm("createpolicy.fractional.L2::evict_last.b64 %0, 1.0;" : "=l"(pol));

    int row0 = blockIdx.x * ROWS_PER_BLOCK;
    int c = threadIdx.x;                       // 32B slot 0..127

    // Uniform index loads: 8 ints as two int4 (32B-aligned since row0%8==0)
    int4 ia = __ldg((const int4*)(x + row0));
    int4 ib = __ldg((const int4*)(x + row0 + 4));

    const float* base = w + (size_t)c * 8;

    // Front-batched independent gathers: MLP = 8 x 256-bit, L2-pinned
    f8 v0 = ldg8_el(base + (size_t)ia.x * EMB_DIM, pol);
    f8 v1 = ldg8_el(base + (size_t)ia.y * EMB_DIM, pol);
    f8 v2 = ldg8_el(base + (size_t)ia.z * EMB_DIM, pol);
    f8 v3 = ldg8_el(base + (size_t)ia.w * EMB_DIM, pol);
    f8 v4 = ldg8_el(base + (size_t)ib.x * EMB_DIM, pol);
    f8 v5 = ldg8_el(base + (size_t)ib.y * EMB_DIM, pol);
    f8 v6 = ldg8_el(base + (size_t)ib.z * EMB_DIM, pol);
    f8 v7 = ldg8_el(base + (size_t)ib.w * EMB_DIM, pol);

    // Streaming 256-bit stores: keep the write stream OUT of L2
    float* dst = out + (size_t)row0 * EMB_DIM + (size_t)c * 8;
    stg8_cs(dst + 0 * EMB_DIM, v0);
    stg8_cs(dst + 1 * EMB_DIM, v1);
    stg8_cs(dst + 2 * EMB_DIM, v2);
    stg8_cs(dst + 3 * EMB_DIM, v3);
    stg8_cs(dst + 4 * EMB_DIM, v4);
    stg8_cs(dst + 5 * EMB_DIM, v5);
    stg8_cs(dst + 6 * EMB_DIM, v6);
    stg8_cs(dst + 7 * EMB_DIM, v7);
}

extern "C" void kernel_launch(void* const* d_in, const int* in_sizes, int n_in,
                              void* d_out, int out_size) {
    const int*   x = (const int*)d_in[0];          // [16384] indices
    const float* w = (const float*)d_in[1];        // [50257*1024] fp32
    float*       o = (float*)d_out;

    int n_rows = in_sizes[0];                      // 16384
    int n_blocks = n_rows / ROWS_PER_BLOCK;        // 2048
    embedding_gather_kernel<<<n_blocks, 128>>>(x, w, o, n_rows);
}

// round 12
// speedup vs baseline: 1.2910x; 1.2910x over previous
#include <cuda_runtime.h>
#include <cuda_bf16.h>
#include <cstdint>

// Embedding gather: out[row, :] = w[x[row], :]
// x: [16384] int32, w: [50257, 1024] fp32, out: [16384, 1024] fp32
//
// Proven-best memory policy (measured over 10 rounds):
//   - gathered w rows: ld.global.nc + L2::evict_last (hot ~57 MB L2-resident
//     across graph replays; worth ~0.3 us)
//   - out: st.global.cs streaming stores (any L2-retention store policy costs
//     ~4.5 us by thrashing the read set)
//   - 4 rows per group, 256 threads, one float4 column slot per thread (MLP=4)
// This round: persistent single-wave schedule. 148x8 = 1184 CTAs, grid-stride
// loop over the 4096 row-groups. Removes 2-3 wave transitions and keeps the
// per-SM load pipeline primed across loop iterations.

#define EMB_DIM 1024
#define VEC_PER_ROW (EMB_DIM / 4)   // 256 float4 per row
#define ROWS_PER_GROUP 4
#define PERSISTENT_CTAS (148 * 8)

__device__ __forceinline__ float4 ldg_el(const float4* p, uint64_t pol) {
    float4 v;
    asm volatile("ld.global.nc.L2::cache_hint.v4.f32 {%0,%1,%2,%3}, [%4], %5;"
                 : "=f"(v.x), "=f"(v.y), "=f"(v.z), "=f"(v.w)
                 : "l"(p), "l"(pol));
    return v;
}

__device__ __forceinline__ void stcs_f4(float4* p, float4 v) {
    asm volatile("st.global.cs.v4.f32 [%0], {%1,%2,%3,%4};"
                 :: "l"(p), "f"(v.x), "f"(v.y), "f"(v.z), "f"(v.w) : "memory");
}

__global__ void __launch_bounds__(256, 8) embedding_gather_kernel(
    const int* __restrict__ x,
    const float4* __restrict__ w,
    float4* __restrict__ out,
    int n_groups)
{
    uint64_t pol;
    asm("createpolicy.fractional.L2::evict_last.b64 %0, 1.0;" : "=l"(pol));

    int c = threadIdx.x;                       // column slot 0..255
    const float4* base = w + c;

    for (int g = blockIdx.x; g < n_groups; g += gridDim.x) {
        int row0 = g * ROWS_PER_GROUP;

        // Uniform index load: 4 ints as one int4 (16B-aligned)
        int4 ia = __ldg((const int4*)(x + row0));

        // Front-batched independent gathers: MLP = 4, L2-pinned
        float4 v0 = ldg_el(base + (size_t)ia.x * VEC_PER_ROW, pol);
        float4 v1 = ldg_el(base + (size_t)ia.y * VEC_PER_ROW, pol);
        float4 v2 = ldg_el(base + (size_t)ia.z * VEC_PER_ROW, pol);
        float4 v3 = ldg_el(base + (size_t)ia.w * VEC_PER_ROW, pol);

        // Streaming stores: keep the write stream OUT of L2
        float4* dst = out + (size_t)row0 * VEC_PER_ROW + c;
        stcs_f4(dst + 0 * VEC_PER_ROW, v0);
        stcs_f4(dst + 1 * VEC_PER_ROW, v1);
        stcs_f4(dst + 2 * VEC_PER_ROW, v2);
        stcs_f4(dst + 3 * VEC_PER_ROW, v3);
    }
}

extern "C" void kernel_launch(void* const* d_in, const int* in_sizes, int n_in,
                              void* d_out, int out_size) {
    const int*    x = (const int*)d_in[0];          // [16384] indices
    const float4* w = (const float4*)d_in[1];       // [50257*1024] fp32 as float4
    float4*       o = (float4*)d_out;

    int n_rows = in_sizes[0];                       // 16384
    int n_groups = n_rows / ROWS_PER_GROUP;         // 4096
    int n_blocks = PERSISTENT_CTAS;                 // 1184: one full wave
    if (n_blocks > n_groups) n_blocks = n_groups;
    embedding_gather_kernel<<<n_blocks, 256>>>(x, w, o, n_groups);
}